// round 2
// baseline (speedup 1.0000x reference)
#include <cuda_runtime.h>

// LIF update: elementwise over N = 64*256*32*32 = 16,777,216 f32 elements.
// Inputs (metadata order): impulse, mem, refrac_until, spiketrain (values unused).
// Output: 4*N floats: [psp | mem_out | refrac_out | spiketrain_out].
//
// Round 2: single-wave grid-stride (1024 CTAs x 256 thr = 2^18 threads,
// exactly 16 iters over n4 = 2^22 float4s), unrolled x4 for deep MLP,
// streaming cache hints (__ldcs/__stcs) since there is zero reuse.

__device__ __forceinline__ void lif_lane(float imp, float m, float ru,
                                         float& psp, float& mo, float& ro, float& so)
{
    const float TIME = 5.0f;
    const float REFRAC_RESET = 7.0f;   // TIME + TAU_REFRAC
    const float V_THRESH = 1.0f;
    const float LEAK_AMT = 0.1f;       // 0.1 * DT

    float mi = (ru > TIME) ? 0.0f : imp;
    float nm = m + mi;
    nm = (nm > 0.0f) ? nm - LEAK_AMT : nm;
    bool sp = (nm >= V_THRESH);
    psp = sp ? V_THRESH : 0.0f;
    mo  = sp ? 0.0f : nm;
    ro  = sp ? REFRAC_RESET : ru;
    so  = sp ? TIME : 0.0f;
}

__global__ void __launch_bounds__(256) spike_layer_kernel(
    const float4* __restrict__ impulse,
    const float4* __restrict__ mem,
    const float4* __restrict__ refrac_until,
    float4* __restrict__ out_psp,
    float4* __restrict__ out_mem,
    float4* __restrict__ out_refrac,
    float4* __restrict__ out_spiketrain,
    int n4)
{
    const int stride = gridDim.x * blockDim.x;
    int i = blockIdx.x * blockDim.x + threadIdx.x;

    #pragma unroll 4
    for (; i < n4; i += stride) {
        float4 imp = __ldcs(&impulse[i]);
        float4 m   = __ldcs(&mem[i]);
        float4 ru  = __ldcs(&refrac_until[i]);

        float4 psp, mo, ro, so;
        lif_lane(imp.x, m.x, ru.x, psp.x, mo.x, ro.x, so.x);
        lif_lane(imp.y, m.y, ru.y, psp.y, mo.y, ro.y, so.y);
        lif_lane(imp.z, m.z, ru.z, psp.z, mo.z, ro.z, so.z);
        lif_lane(imp.w, m.w, ru.w, psp.w, mo.w, ro.w, so.w);

        __stcs(&out_psp[i],        psp);
        __stcs(&out_mem[i],        mo);
        __stcs(&out_refrac[i],     ro);
        __stcs(&out_spiketrain[i], so);
    }
}

extern "C" void kernel_launch(void* const* d_in, const int* in_sizes, int n_in,
                              void* d_out, int out_size)
{
    const float* impulse      = (const float*)d_in[0];
    const float* mem          = (const float*)d_in[1];
    const float* refrac_until = (const float*)d_in[2];
    // d_in[3] (spiketrain) values are unused by the reference math.

    int n = in_sizes[0];          // 16,777,216
    int n4 = n / 4;               // 4,194,304 = 2^22

    float* out = (float*)d_out;   // [psp | mem | refrac | spiketrain], each n floats

    // Single wave: 1024 blocks x 256 threads = 2^18 threads -> 16 iters/thread.
    // 1024 CTAs over 148+ SMs at <=8 CTAs/SM resident -> one wave, no transitions.
    int threads = 256;
    int blocks  = 1024;

    spike_layer_kernel<<<blocks, threads>>>(
        (const float4*)impulse,
        (const float4*)mem,
        (const float4*)refrac_until,
        (float4*)(out),
        (float4*)(out + (size_t)n),
        (float4*)(out + (size_t)2 * n),
        (float4*)(out + (size_t)3 * n),
        n4);
}

// round 3
// speedup vs baseline: 1.1703x; 1.1703x over previous
#include <cuda_runtime.h>

// LIF update: elementwise over N = 64*256*32*32 = 16,777,216 f32 elements.
// Inputs (metadata order): impulse, mem, refrac_until, spiketrain (values unused).
// Output: 4*N floats: [psp | mem_out | refrac_out | spiketrain_out].
//
// Round 3: R1 launch shape (16384 CTAs x 256 thr, 1 float4/thread -> max
// resident warps) + streaming cache hints (__ldcs/__stcs) as the ONLY change
// vs R1. R2 showed grid-stride @1024 CTAs loses occupancy and regresses.

__device__ __forceinline__ void lif_lane(float imp, float m, float ru,
                                         float& psp, float& mo, float& ro, float& so)
{
    const float TIME = 5.0f;
    const float REFRAC_RESET = 7.0f;   // TIME + TAU_REFRAC
    const float V_THRESH = 1.0f;
    const float LEAK_AMT = 0.1f;       // 0.1 * DT

    float mi = (ru > TIME) ? 0.0f : imp;
    float nm = m + mi;
    nm = (nm > 0.0f) ? nm - LEAK_AMT : nm;
    bool sp = (nm >= V_THRESH);
    psp = sp ? V_THRESH : 0.0f;
    mo  = sp ? 0.0f : nm;
    ro  = sp ? REFRAC_RESET : ru;
    so  = sp ? TIME : 0.0f;
}

__global__ void __launch_bounds__(256) spike_layer_kernel(
    const float4* __restrict__ impulse,
    const float4* __restrict__ mem,
    const float4* __restrict__ refrac_until,
    float4* __restrict__ out_psp,
    float4* __restrict__ out_mem,
    float4* __restrict__ out_refrac,
    float4* __restrict__ out_spiketrain,
    int n4)
{
    int i = blockIdx.x * blockDim.x + threadIdx.x;
    if (i >= n4) return;

    float4 imp = __ldcs(&impulse[i]);
    float4 m   = __ldcs(&mem[i]);
    float4 ru  = __ldcs(&refrac_until[i]);

    float4 psp, mo, ro, so;
    lif_lane(imp.x, m.x, ru.x, psp.x, mo.x, ro.x, so.x);
    lif_lane(imp.y, m.y, ru.y, psp.y, mo.y, ro.y, so.y);
    lif_lane(imp.z, m.z, ru.z, psp.z, mo.z, ro.z, so.z);
    lif_lane(imp.w, m.w, ru.w, psp.w, mo.w, ro.w, so.w);

    __stcs(&out_psp[i],        psp);
    __stcs(&out_mem[i],        mo);
    __stcs(&out_refrac[i],     ro);
    __stcs(&out_spiketrain[i], so);
}

extern "C" void kernel_launch(void* const* d_in, const int* in_sizes, int n_in,
                              void* d_out, int out_size)
{
    const float* impulse      = (const float*)d_in[0];
    const float* mem          = (const float*)d_in[1];
    const float* refrac_until = (const float*)d_in[2];
    // d_in[3] (spiketrain) values are unused by the reference math.

    int n = in_sizes[0];          // 16,777,216
    int n4 = n / 4;               // 4,194,304 = 2^22

    float* out = (float*)d_out;   // [psp | mem | refrac | spiketrain], each n floats

    int threads = 256;
    int blocks = (n4 + threads - 1) / threads;   // 16384

    spike_layer_kernel<<<blocks, threads>>>(
        (const float4*)impulse,
        (const float4*)mem,
        (const float4*)refrac_until,
        (float4*)(out),
        (float4*)(out + (size_t)n),
        (float4*)(out + (size_t)2 * n),
        (float4*)(out + (size_t)3 * n),
        n4);
}